// round 1
// baseline (speedup 1.0000x reference)
#include <cuda_runtime.h>
#include <math.h>

// ---------------------------------------------------------------------------
// QuantumDenseNet: CV quantum circuit simulator.
// C=6 Fock levels, N=5 modes, state = 6^5 = 7776 complex per batch element.
// Strategy:
//   1) prep_bs_kernel / prep_sm_kernel: compute all batch-independent gate
//      matrices (80x 36x36 BS expm, 40x 6x6 squeeze/disp expm) into device
//      globals.
//   2) qnet_kernel: one CTA per batch element; full state lives in shared
//      memory (62KB); apply all gates in smem; diagonal gates (rot/kerr)
//      fused across modes; tridiagonal expectation at the end.
// ---------------------------------------------------------------------------

__device__ float2 g_bs[80][1296];  // beamsplitter gates, row-major [out36][in36]
__device__ float2 g_sm[40][36];    // per layer: 5 squeeze then 5 disp, 6x6

__device__ __forceinline__ void cmadd(float2& a, float2 u, float2 v) {
    a.x = fmaf(u.x, v.x, fmaf(-u.y, v.y, a.x));
    a.y = fmaf(u.x, v.y, fmaf(u.y, v.x, a.y));
}
__device__ __forceinline__ float2 cmul(float2 u, float2 v) {
    return make_float2(u.x * v.x - u.y * v.y, u.x * v.y + u.y * v.x);
}

// ---------------------------------------------------------------------------
// Precompute: beamsplitter gates.
// H[(a,b),(c,d)] = theta * ( e^{i phi} * A[a,c]*AD[b,d] - e^{-i phi} * AD[a,c]*A[b,d] )
// A[i][i+1] = sqrt(i+1) (superdiagonal), AD = A^T.
// expm: order-16 Horner Taylor + 6 squarings (matches reference _expm).
// ---------------------------------------------------------------------------
__global__ void prep_bs_kernel(const float* __restrict__ lin) {
    __shared__ float2 sH[1296], sA[1296], sB[1296];
    int gid = blockIdx.x;                  // 0..79
    int l = gid / 20, rem = gid % 20, h = rem / 10, n = rem % 10;
    const float* p = lin + l * 63;
    float theta = h ? p[29 + n] : p[n];
    float phi   = h ? p[39 + n] : p[10 + n];
    float sp, cp;
    sincosf(phi, &sp, &cp);
    int tid = threadIdx.x;

    for (int e = tid; e < 1296; e += blockDim.x) {
        int row = e / 36, col = e % 36;
        int a = row / 6, bq = row % 6, c = col / 6, d = col % 6;
        float2 v = make_float2(0.f, 0.f);
        if (c == a + 1 && d == bq - 1) {         // ep * kron(A, AD)
            float m = theta * sqrtf((float)((a + 1) * bq));
            v.x += m * cp; v.y += m * sp;
        }
        if (c == a - 1 && d == bq + 1) {         // -conj(ep) * kron(AD, A)
            float m = theta * sqrtf((float)(a * (bq + 1)));
            v.x -= m * cp; v.y += m * sp;
        }
        sH[e] = make_float2(v.x * (1.f / 64.f), v.y * (1.f / 64.f));
        sA[e] = make_float2(row == col ? 1.f : 0.f, 0.f);
    }
    __syncthreads();

    float2* pa = sA;
    float2* pb = sB;
    for (int k = 16; k >= 1; k--) {
        float inv = 1.f / (float)k;
        for (int e = tid; e < 1296; e += blockDim.x) {
            int row = e / 36, col = e % 36;
            float2 acc = make_float2(0.f, 0.f);
            for (int j = 0; j < 36; j++) cmadd(acc, sH[row * 36 + j], pa[j * 36 + col]);
            pb[e] = make_float2((row == col ? 1.f : 0.f) + acc.x * inv, acc.y * inv);
        }
        __syncthreads();
        float2* t = pa; pa = pb; pb = t;
    }
    for (int s = 0; s < 6; s++) {
        for (int e = tid; e < 1296; e += blockDim.x) {
            int row = e / 36, col = e % 36;
            float2 acc = make_float2(0.f, 0.f);
            for (int j = 0; j < 36; j++) cmadd(acc, pa[row * 36 + j], pa[j * 36 + col]);
            pb[e] = acc;
        }
        __syncthreads();
        float2* t = pa; pa = pb; pb = t;
    }
    for (int e = tid; e < 1296; e += blockDim.x) g_bs[gid][e] = pa[e];
}

// ---------------------------------------------------------------------------
// Precompute: squeeze (gid%10 < 5) and displacement (gid%10 >= 5) 6x6 gates.
// squeeze: G = r*0.5*(A@A - AD@AD)   (real)
// disp:    G = al*AD - conj(al)*A,  al = dr * e^{i dp}
// ---------------------------------------------------------------------------
__global__ void prep_sm_kernel(const float* __restrict__ lin) {
    __shared__ float2 sH[36], sA[36], sB[36];
    int gid = blockIdx.x;                 // 0..39
    int l = gid / 10, r10 = gid % 10;
    int isdisp = (r10 >= 5);
    int i = r10 % 5;
    const float* p = lin + l * 63;
    int e = threadIdx.x;                  // blockDim = 36
    int row = e / 6, col = e % 6;

    float2 hv = make_float2(0.f, 0.f);
    if (!isdisp) {
        float rr = p[24 + i];
        if (col == row + 2) hv.x = rr * 0.5f * sqrtf((float)((row + 1) * (row + 2)));
        if (row == col + 2) hv.x = -rr * 0.5f * sqrtf((float)((col + 1) * (col + 2)));
    } else {
        float dr = p[53 + i], dphi = p[58 + i];
        float s, c;
        sincosf(dphi, &s, &c);
        if (row == col + 1) { float m = dr * sqrtf((float)row); hv.x = m * c;  hv.y = m * s; }
        if (col == row + 1) { float m = dr * sqrtf((float)col); hv.x = -m * c; hv.y = m * s; }
    }
    sH[e] = make_float2(hv.x * (1.f / 64.f), hv.y * (1.f / 64.f));
    sA[e] = make_float2(row == col ? 1.f : 0.f, 0.f);
    __syncthreads();

    float2* pa = sA;
    float2* pb = sB;
    for (int k = 16; k >= 1; k--) {
        float inv = 1.f / (float)k;
        float2 acc = make_float2(0.f, 0.f);
        #pragma unroll
        for (int j = 0; j < 6; j++) cmadd(acc, sH[row * 6 + j], pa[j * 6 + col]);
        pb[e] = make_float2((row == col ? 1.f : 0.f) + acc.x * inv, acc.y * inv);
        __syncthreads();
        float2* t = pa; pa = pb; pb = t;
    }
    for (int s = 0; s < 6; s++) {
        float2 acc = make_float2(0.f, 0.f);
        #pragma unroll
        for (int j = 0; j < 6; j++) cmadd(acc, pa[row * 6 + j], pa[j * 6 + col]);
        pb[e] = acc;
        __syncthreads();
        float2* t = pa; pa = pb; pb = t;
    }
    g_sm[gid][e] = pa[e];
}

// ---------------------------------------------------------------------------
// Main kernel helpers (state + scratch in dynamic smem)
// ---------------------------------------------------------------------------

// Single-mode 6x6 gate on mode m. Mode-m stride = 6^(4-m). Fiber-per-thread:
// each thread owns a whole length-6 fiber -> in-place safe.
__device__ __forceinline__ void apply_sm(float2* psi, float2* sU, int tid,
                                         const float2* __restrict__ Ug, int m) {
    if (tid < 36) sU[tid] = Ug[tid];
    __syncthreads();
    int s = (m == 0) ? 1296 : (m == 1) ? 216 : (m == 2) ? 36 : (m == 3) ? 6 : 1;
    for (int f = tid; f < 1296; f += 256) {
        int hi = f / s, lo = f - hi * s;
        int base = hi * (s * 6) + lo;
        float2 xv[6];
        #pragma unroll
        for (int t = 0; t < 6; t++) xv[t] = psi[base + t * s];
        #pragma unroll
        for (int r = 0; r < 6; r++) {
            float2 a = make_float2(0.f, 0.f);
            #pragma unroll
            for (int t = 0; t < 6; t++) cmadd(a, sU[r * 6 + t], xv[t]);
            psi[base + r * s] = a;
        }
    }
    __syncthreads();
}

// Beamsplitter 36x36 gate on modes (m, m+1). Modes m,m+1 fuse into one index
// e = c*6+d with stride s = 6^(3-m). 216 fibers, one per thread, full 36
// complex accumulators in registers -> in-place safe.
__device__ __forceinline__ void apply_bs(float2* psi, float2* sU, int tid,
                                         const float2* __restrict__ Ug, int m) {
    for (int i = tid; i < 1296; i += 256) sU[i] = Ug[i];
    __syncthreads();
    int s = (m == 0) ? 216 : (m == 1) ? 36 : (m == 2) ? 6 : 1;
    if (tid < 216) {
        int hi = tid / s, lo = tid - hi * s;
        int base = hi * (s * 36) + lo;
        float2 acc[36];
        #pragma unroll
        for (int r = 0; r < 36; r++) acc[r] = make_float2(0.f, 0.f);
        #pragma unroll 4
        for (int j = 0; j < 36; j++) {
            float2 xv = psi[base + j * s];
            #pragma unroll
            for (int r = 0; r < 36; r++) cmadd(acc[r], sU[r * 36 + j], xv);
        }
        #pragma unroll
        for (int r = 0; r < 36; r++) psi[base + r * s] = acc[r];
    }
    __syncthreads();
}

// Fused diagonal gate: rot (phase p*n) over nmodes modes, or kerr (p*n^2).
// Modes beyond nmodes get identity.
__device__ __forceinline__ void apply_diag(float2* psi, float2* sD, int tid,
                                           const float* __restrict__ params,
                                           int nmodes, bool kerr) {
    if (tid < 30) {
        int mm = tid / 6, n = tid % 6;
        float ph = 0.f;
        if (mm < nmodes) {
            float pv = params[mm];
            ph = kerr ? pv * (float)(n * n) : pv * (float)n;
        }
        float s, c;
        sincosf(ph, &s, &c);
        sD[tid] = make_float2(c, s);
    }
    __syncthreads();
    for (int idx = tid; idx < 7776; idx += 256) {
        int t2 = idx;
        int n4 = t2 % 6; t2 /= 6;
        int n3 = t2 % 6; t2 /= 6;
        int n2 = t2 % 6; t2 /= 6;
        int n1 = t2 % 6;
        int n0 = t2 / 6;
        float2 f = cmul(sD[n0], sD[6 + n1]);
        f = cmul(f, sD[12 + n2]);
        f = cmul(f, sD[18 + n3]);
        f = cmul(f, sD[24 + n4]);
        psi[idx] = cmul(psi[idx], f);
    }
    __syncthreads();
}

// ---------------------------------------------------------------------------
// Main kernel: one CTA per batch element.
// Dynamic smem: psi[7776] float2 (62208B) + scratch sU[1296] float2 (10368B)
// ---------------------------------------------------------------------------
__global__ __launch_bounds__(256, 2)
void qnet_kernel(const float* __restrict__ x, const float* __restrict__ lin,
                 const float* __restrict__ act, const float* __restrict__ lact,
                 float* __restrict__ out) {
    extern __shared__ float2 smem[];
    float2* psi = smem;            // 7776
    float2* sU  = smem + 7776;     // 1296 (gate stage / diag table / scratch)
    float*  sS  = (float*)sU;      // scratch viewed as floats (2592 floats)
    const int tid = threadIdx.x;
    const int b = blockIdx.x;

    // ---- initial displacement vectors: v_i = col0 of expm(x_i*(AD - A)) ----
    // generator is real -> real 6x6 expm, 5 modes in parallel (180 threads).
    {
        float* sG  = sS;           // 180 floats
        float* sR0 = sS + 180;     // 180
        float* sR1 = sS + 360;     // 180
        float* sV  = sS + 540;     // 30
        int g = tid / 36, e = tid % 36;
        bool on = (tid < 180);
        int row = e / 6, col = e % 6;
        if (on) {
            float xv = x[b * 5 + g];
            float gv = 0.f;
            if (row == col + 1) gv += sqrtf((float)row);   // AD
            if (col == row + 1) gv -= sqrtf((float)col);   // -A
            sG[g * 36 + e] = xv * gv * (1.f / 64.f);
            sR0[g * 36 + e] = (row == col) ? 1.f : 0.f;
        }
        __syncthreads();
        float* pa = sR0;
        float* pb = sR1;
        for (int k = 16; k >= 1; k--) {
            if (on) {
                float acc = 0.f;
                #pragma unroll
                for (int j = 0; j < 6; j++) acc += sG[g * 36 + row * 6 + j] * pa[g * 36 + j * 6 + col];
                pb[g * 36 + e] = ((row == col) ? 1.f : 0.f) + acc * (1.f / (float)k);
            }
            __syncthreads();
            float* t = pa; pa = pb; pb = t;
        }
        for (int s = 0; s < 6; s++) {
            if (on) {
                float acc = 0.f;
                #pragma unroll
                for (int j = 0; j < 6; j++) acc += pa[g * 36 + row * 6 + j] * pa[g * 36 + j * 6 + col];
                pb[g * 36 + e] = acc;
            }
            __syncthreads();
            float* t = pa; pa = pb; pb = t;
        }
        if (on && col == 0) sV[g * 6 + row] = pa[g * 36 + row * 6];
        __syncthreads();

        // psi = outer product of the 5 displacement columns (real)
        for (int idx = tid; idx < 7776; idx += 256) {
            int t2 = idx;
            int n4 = t2 % 6; t2 /= 6;
            int n3 = t2 % 6; t2 /= 6;
            int n2 = t2 % 6; t2 /= 6;
            int n1 = t2 % 6;
            int n0 = t2 / 6;
            float v = sV[n0] * sV[6 + n1] * sV[12 + n2] * sV[18 + n3] * sV[24 + n4];
            psi[idx] = make_float2(v, 0.f);
        }
        __syncthreads();
    }

    // ---- circuit ----
    const int km[10] = {0, 2, 1, 3, 0, 2, 1, 3, 0, 2};
    for (int l = 0; l < 4; l++) {
        const float* p = lin + l * 63;
        for (int n = 0; n < 10; n++) apply_bs(psi, sU, tid, g_bs[l * 20 + n], km[n]);
        apply_diag(psi, sU, tid, p + 20, 4, false);                         // rot 1
        for (int i = 0; i < 5; i++) apply_sm(psi, sU, tid, g_sm[l * 10 + i], i);       // squeeze
        for (int n = 0; n < 10; n++) apply_bs(psi, sU, tid, g_bs[l * 20 + 10 + n], km[n]);
        apply_diag(psi, sU, tid, p + 49, 4, false);                         // rot 2
        for (int i = 0; i < 5; i++) apply_sm(psi, sU, tid, g_sm[l * 10 + 5 + i], i);   // disp
        if (l < 3) apply_diag(psi, sU, tid, act + l * 5, 5, true);          // kerr
    }
    apply_diag(psi, sU, tid, lact, 2, true);                                // final kerr (2 modes)

    // ---- expectation <psi| (A+AD)_i |psi> = 2*sum sqrt(n+1) Re(conj(psi_n) psi_{n+1}) ----
    float s0 = 0.f, s1 = 0.f;
    for (int idx = tid; idx < 7776; idx += 256) {
        float2 a = psi[idx];
        int n0 = idx / 1296;
        int n1 = (idx / 216) % 6;
        if (n0 < 5) {
            float2 bb = psi[idx + 1296];
            s0 += sqrtf((float)(n0 + 1)) * (a.x * bb.x + a.y * bb.y);
        }
        if (n1 < 5) {
            float2 bb = psi[idx + 216];
            s1 += sqrtf((float)(n1 + 1)) * (a.x * bb.x + a.y * bb.y);
        }
    }
    #pragma unroll
    for (int off = 16; off; off >>= 1) {
        s0 += __shfl_down_sync(0xffffffffu, s0, off);
        s1 += __shfl_down_sync(0xffffffffu, s1, off);
    }
    __syncthreads();   // psi reads done before scratch reuse
    float* sRed = sS;
    if ((tid & 31) == 0) {
        sRed[(tid >> 5) * 2] = s0;
        sRed[(tid >> 5) * 2 + 1] = s1;
    }
    __syncthreads();
    if (tid == 0) {
        float t0 = 0.f, t1 = 0.f;
        for (int w = 0; w < 8; w++) { t0 += sRed[2 * w]; t1 += sRed[2 * w + 1]; }
        out[b * 2 + 0] = 2.f * t0;
        out[b * 2 + 1] = 2.f * t1;
    }
}

// ---------------------------------------------------------------------------
extern "C" void kernel_launch(void* const* d_in, const int* in_sizes, int n_in,
                              void* d_out, int out_size) {
    const float* x    = (const float*)d_in[0];   // (B,5)
    const float* lin  = (const float*)d_in[1];   // (4,63)
    const float* act  = (const float*)d_in[2];   // (3,5)
    const float* lact = (const float*)d_in[3];   // (5,)
    float* out = (float*)d_out;                  // (B,2)
    int B = in_sizes[0] / 5;

    cudaFuncSetAttribute(qnet_kernel, cudaFuncAttributeMaxDynamicSharedMemorySize, 72576);

    prep_bs_kernel<<<80, 256>>>(lin);
    prep_sm_kernel<<<40, 36>>>(lin);
    qnet_kernel<<<B, 256, 72576>>>(x, lin, act, lact, out);
}